// round 13
// baseline (speedup 1.0000x reference)
#include <cuda_runtime.h>
#include <cuda_fp16.h>
#include <cstdint>

#define GATES 255
#define BM    64
#define NT    256

// Fragment-major fp16 weights, Kc=32 tiles (rebuilt every call, deterministic).
__device__ __half g_gwH[512 * 256];   // 16 tiles of [32k][256n] (8192 halves each)
__device__ __half g_zH [256 * 256];   // 8 tiles

// ---- smem layout (bytes), 74240 total -> 3 CTAs/SM ----
// gates(fp16) overlaps the GEMM bufs (disjoint lifetimes, sync-separated);
// gbs overlaps leaf head (gbs last read in sigmoid; leaf written after next sync).
#define A_OFF(b)   ((unsigned)(b) * 4096u)              // A frag [64m][32k] fp16, x2
#define B_OFF(b)   (8192u + (unsigned)(b) * 16384u)     // B frag [256n][32k] fp16, x2 (ends 40960)
#define GATES_OFF  0u                                   // gates [64][258] fp16 (33024 B)
#define LEAF_OFF   40960u                               // leaf  [64][260] fp16 (33280 B)
#define GBS_OFF    40960u                               // 256 f32 (overlaps leaf head)
#define SMEM_BYTES 74240u
#define GGLS 258   // halves; 516 B stride (129 words, coprime 32 -> conflict-free rows)
#define LLS  260   // halves; 520 B stride (8-aligned for uint2)

__device__ __forceinline__ uint32_t smem_u32(const void* p) {
    uint32_t a;
    asm("{ .reg .u64 t; cvta.to.shared.u64 t, %1; cvt.u32.u64 %0, t; }" : "=r"(a) : "l"(p));
    return a;
}
#define CP_ASYNC16(dst, src) \
    asm volatile("cp.async.cg.shared.global [%0], [%1], 16;" :: "r"(dst), "l"(src) : "memory")
#define CP_COMMIT() asm volatile("cp.async.commit_group;" ::: "memory")
#define CP_WAIT(n)  asm volatile("cp.async.wait_group %0;" :: "n"(n) : "memory")

__device__ __forceinline__ void mma16(float* c, const uint32_t* a, uint32_t b0, uint32_t b1) {
    asm volatile("mma.sync.aligned.m16n8k16.row.col.f32.f16.f16.f32 "
        "{%0,%1,%2,%3}, {%4,%5,%6,%7}, {%8,%9}, {%0,%1,%2,%3};"
        : "+f"(c[0]), "+f"(c[1]), "+f"(c[2]), "+f"(c[3])
        : "r"(a[0]), "r"(a[1]), "r"(a[2]), "r"(a[3]), "r"(b0), "r"(b1));
}
__device__ __forceinline__ float sigmoidf_fast(float v) {
    return __fdividef(1.0f, 1.0f + __expf(-v));
}

// A-frag STS byte addr (Kc=32) for half-quad (row, q), q in 0..7, k0=4q
__device__ __forceinline__ uint32_t afrag_addr(int row, int q) {
    int ra = row >> 4, ks = q >> 2;
    int lane = (row & 7) * 4 + ((2 * q) & 3);
    int reg  = ((row >> 3) & 1) + 2 * ((q >> 1) & 1);
    return (uint32_t)((ra * 2 + ks) * 512 + lane * 16 + reg * 4);
}

// ---- prep kernel: output-centric; 8 fragment-major halves -> one uint4 ----
// Kc=32 idx decomposition: bit0=k0, bit1=k3, bits[2:4)=k[1:3), bits[4:7)=n[0:3),
// bit7=k4, bits[8:13)=n[3:8), bits13+ = k>>5.
__global__ void prep_kernel(const float* __restrict__ gw, const float* __restrict__ z) {
    const int t8 = (blockIdx.x * 256 + threadIdx.x) * 8;   // 96 blocks -> 196608 halves
    const int koff[8] = {0, 1, 8, 9, 2, 3, 10, 11};
    __half h[8];
    if (t8 < 131072) {            // gw -> g_gwH
        int n    = ((t8 >> 4) & 7) + ((t8 >> 8) & 31) * 8;
        int kfix = ((t8 >> 3) & 1) * 4 + ((t8 >> 7) & 1) * 16 + (t8 >> 13) * 32;
        #pragma unroll
        for (int i = 0; i < 8; i++) {
            int k = kfix + koff[i];
            h[i] = (n < GATES) ? __float2half_rn(gw[k * GATES + n]) : __half(0.0f);
        }
        *(uint4*)&g_gwH[t8] = *(const uint4*)h;
    } else {                      // z -> g_zH
        int t8z  = t8 - 131072;
        int n    = ((t8z >> 4) & 7) + ((t8z >> 8) & 31) * 8;
        int kfix = ((t8z >> 3) & 1) * 4 + ((t8z >> 7) & 1) * 16 + (t8z >> 13) * 32;
        #pragma unroll
        for (int i = 0; i < 8; i++) {
            int k = kfix + koff[i];
            h[i] = __float2half_rn(z[n * 256 + k]);
        }
        *(uint4*)&g_zH[t8z] = *(const uint4*)h;
    }
}

// ---- main fused kernel: one CTA = 64 rows, 8 warps (32m x 64n), 3 CTAs/SM ----
extern "C" __global__ void __launch_bounds__(NT, 3)
softtree_h7_kernel(const float* __restrict__ x,
                   const float* __restrict__ gb,
                   float* __restrict__ out)
{
    extern __shared__ char smc[];
    __half* gates = (__half*)(smc + GATES_OFF);
    __half* leaf  = (__half*)(smc + LEAF_OFF);
    float*  gbs   = (float*)(smc + GBS_OFF);
    const uint32_t sb = smem_u32(smc);

    const int tid  = threadIdx.x;
    const int lane = tid & 31;
    const int wid  = tid >> 5;       // 0..7
    const int mg   = wid & 1;        // rows mg*32 .. +31
    const int ng   = wid >> 1;       // cols ng*64 .. +63
    const int g    = lane >> 2;
    const int t4   = lane & 3;
    const int rbase = blockIdx.x * BM;

    gbs[tid] = (tid < GATES) ? gb[tid] : 0.0f;

    float acc[2][8][4];
    #pragma unroll
    for (int ra = 0; ra < 2; ra++)
        #pragma unroll
        for (int j = 0; j < 8; j++)
            #pragma unroll
            for (int e = 0; e < 4; e++) acc[ra][j][e] = 0.0f;

    uint32_t xh[4];

    auto issueB = [&](int buf, const __half* srcTile) {
        const char* s = (const char*)srcTile;
        #pragma unroll
        for (int j = 0; j < 4; j++) {
            uint32_t off = (uint32_t)(tid + j * NT) * 16u;
            CP_ASYNC16(sb + B_OFF(buf) + off, s + off);
        }
    };
    auto ldgA = [&](int t) {
        #pragma unroll
        for (int j = 0; j < 2; j++) {
            int f = j * NT + tid;            // 0..511
            int row = f >> 3, q = f & 7;
            float4 v = *(const float4*)&x[(size_t)(rbase + row) * 512 + t * 32 + q * 4];
            __half2 h0 = __floats2half2_rn(v.x, v.y);
            __half2 h1 = __floats2half2_rn(v.z, v.w);
            xh[2 * j]     = *(uint32_t*)&h0;
            xh[2 * j + 1] = *(uint32_t*)&h1;
        }
    };
    auto stsA = [&](int buf) {
        #pragma unroll
        for (int j = 0; j < 2; j++) {
            int f = j * NT + tid;
            int row = f >> 3, q = f & 7;
            uint32_t a0 = afrag_addr(row, q);
            *(uint32_t*)(smc + A_OFF(buf) + a0)      = xh[2 * j];
            *(uint32_t*)(smc + A_OFF(buf) + a0 + 16) = xh[2 * j + 1];
        }
    };
    auto compute = [&](int ab, int bb) {
        #pragma unroll
        for (int ks = 0; ks < 2; ks++) {
            uint32_t a0[4], a1[4];
            *(uint4*)a0 = *(const uint4*)(smc + A_OFF(ab) + (uint32_t)((4 * mg + ks)     * 512 + lane * 16));
            *(uint4*)a1 = *(const uint4*)(smc + A_OFF(ab) + (uint32_t)((4 * mg + 2 + ks) * 512 + lane * 16));
            #pragma unroll
            for (int j = 0; j < 8; j++) {
                uint2 bv = *(const uint2*)(smc + B_OFF(bb) + (uint32_t)((((ng * 8 + j) * 2 + ks) * 256) + lane * 8));
                mma16(acc[0][j], a0, bv.x, bv.y);
                mma16(acc[1][j], a1, bv.x, bv.y);
            }
        }
    };

    // ============ Phase 1: logits = x @ gwT (16 K-tiles of 32, one sync/tile) ============
    issueB(0, g_gwH);  CP_COMMIT();
    ldgA(0);  stsA(0);  ldgA(1);

    #pragma unroll 1
    for (int u = 0; u < 16; u++) {
        CP_WAIT(0);
        __syncthreads();
        if (u < 15) {
            stsA((u + 1) & 1);
            issueB((u + 1) & 1, g_gwH + (size_t)(u + 1) * 8192);
            CP_COMMIT();
        }
        compute(u & 1, u & 1);
        if (u < 14) ldgA(u + 2);
    }
    __syncthreads();   // last compute retired; A/B dead -> gates region writable

    // ============ bias + sigmoid -> gates (fp16 storage, f32 math) ============
    #pragma unroll
    for (int ra = 0; ra < 2; ra++)
        #pragma unroll
        for (int j = 0; j < 8; j++) {
            int row = mg * 32 + ra * 16 + g;
            int col = ng * 64 + j * 8 + 2 * t4;
            float b0 = gbs[col], b1 = gbs[col + 1];
            *(__half2*)&gates[row * GGLS + col] =
                __floats2half2_rn(sigmoidf_fast(acc[ra][j][0] + b0),
                                  sigmoidf_fast(acc[ra][j][1] + b1));
            *(__half2*)&gates[(row + 8) * GGLS + col] =
                __floats2half2_rn(sigmoidf_fast(acc[ra][j][2] + b0),
                                  sigmoidf_fast(acc[ra][j][3] + b1));
        }
    __syncthreads();   // gates visible; gbs reads done -> leaf (overlapping gbs) writable

    // ============ tree products (f32) -> leaf fp16 ============
    {
        const int r = tid & 63;
        const __half* grow = &gates[r * GGLS];
        #pragma unroll
        for (int s = 0; s < 2; s++) {
            const int h8 = (tid >> 6) + 4 * s;   // 0..7, leaves h8*32 .. +31

            float p;
            { float g0 = __half2float(grow[0]);             p = (h8 >> 2) ? 1.0f - g0 : g0; }
            { float g1 = __half2float(grow[1 + (h8 >> 2)]); p = ((h8 >> 1) & 1) ? p - p * g1 : p * g1; }
            { float g2 = __half2float(grow[3 + (h8 >> 1)]); p = (h8 & 1) ? p - p * g2 : p * g2; }
            float Q1[2];
            { float gg = __half2float(grow[7 + h8]); Q1[0] = p * gg; Q1[1] = p - Q1[0]; }
            float Q2[4];
            #pragma unroll
            for (int i = 0; i < 2; i++) {
                float gg = __half2float(grow[15 + 2 * h8 + i]);
                Q2[2 * i] = Q1[i] * gg; Q2[2 * i + 1] = Q1[i] - Q2[2 * i];
            }
            float Q3[8];
            #pragma unroll
            for (int i = 0; i < 4; i++) {
                float gg = __half2float(grow[31 + 4 * h8 + i]);
                Q3[2 * i] = Q2[i] * gg; Q3[2 * i + 1] = Q2[i] - Q3[2 * i];
            }
            __half* lrow = &leaf[r * LLS + h8 * 32];
            #pragma unroll
            for (int i = 0; i < 8; i++) {
                float gg = __half2float(grow[63 + 8 * h8 + i]);
                float qa = Q3[i] * gg, qb = Q3[i] - qa;
                float g5a = __half2float(grow[127 + 16 * h8 + 2 * i]);
                float v0 = qa * g5a, v1 = qa - v0;
                *(__half2*)&lrow[4 * i] = __floats2half2_rn(v0, v1);
                float g5b = __half2float(grow[127 + 16 * h8 + 2 * i + 1]);
                float v2 = qb * g5b, v3 = qb - v2;
                *(__half2*)&lrow[4 * i + 2] = __floats2half2_rn(v2, v3);
            }
        }
    }
    __syncthreads();   // all gates reads retired -> A/B bufs (overlapping gates) reusable

    // ============ Phase 3: out = leaf @ z^T (8 K-tiles of 32, one sync/tile) ============
    #pragma unroll
    for (int ra = 0; ra < 2; ra++)
        #pragma unroll
        for (int j = 0; j < 8; j++)
            #pragma unroll
            for (int e = 0; e < 4; e++) acc[ra][j][e] = 0.0f;

    auto fillA = [&](int t, int buf) {
        #pragma unroll
        for (int j = 0; j < 2; j++) {
            int f = j * NT + tid;
            int row = f >> 3, q = f & 7;
            uint2 u2 = *(const uint2*)&leaf[row * LLS + t * 32 + q * 4];
            uint32_t a0 = afrag_addr(row, q);
            *(uint32_t*)(smc + A_OFF(buf) + a0)      = u2.x;
            *(uint32_t*)(smc + A_OFF(buf) + a0 + 16) = u2.y;
        }
    };

    issueB(0, g_zH);  CP_COMMIT();
    fillA(0, 0);

    #pragma unroll 1
    for (int u = 0; u < 8; u++) {
        CP_WAIT(0);
        __syncthreads();
        if (u < 7) {
            fillA(u + 1, (u + 1) & 1);
            issueB((u + 1) & 1, g_zH + (size_t)(u + 1) * 8192);
            CP_COMMIT();
        }
        compute(u & 1, u & 1);
    }

    // ============ write out ============
    #pragma unroll
    for (int ra = 0; ra < 2; ra++)
        #pragma unroll
        for (int j = 0; j < 8; j++) {
            int row = rbase + mg * 32 + ra * 16 + g;
            int col = ng * 64 + j * 8 + 2 * t4;
            float2 s0, s1;
            s0.x = acc[ra][j][0]; s0.y = acc[ra][j][1];
            s1.x = acc[ra][j][2]; s1.y = acc[ra][j][3];
            *(float2*)&out[(size_t)row * 256 + col]       = s0;
            *(float2*)&out[(size_t)(row + 8) * 256 + col] = s1;
        }
}

extern "C" void kernel_launch(void* const* d_in, const int* in_sizes, int n_in,
                              void* d_out, int out_size)
{
    const float* x  = (const float*)d_in[0];   // [B, 512]
    const float* gw = (const float*)d_in[1];   // [512, 255]
    const float* gb = (const float*)d_in[2];   // [255]
    const float* z  = (const float*)d_in[3];   // [256, 256]
    float* out = (float*)d_out;                // [B, 256]

    const int B = in_sizes[0] / 512;

    prep_kernel<<<96, 256>>>(gw, z);

    cudaFuncSetAttribute(softtree_h7_kernel,
                         cudaFuncAttributeMaxDynamicSharedMemorySize, SMEM_BYTES);
    softtree_h7_kernel<<<B / BM, NT, SMEM_BYTES>>>(x, gb, out);
}

// round 14
// speedup vs baseline: 1.5690x; 1.5690x over previous
#include <cuda_runtime.h>
#include <cuda_fp16.h>
#include <cstdint>

#define GATES 255
#define BM    64
#define NT    256

// Fragment-major fp16 weights, Kc=64 tiles (rebuilt every call, deterministic).
// B layout per tile (16384 halves): group(ng*4+ks)*1024 + q*256 + lane*8 + rl*2 + half
//   where j=(n>>3)&7, q=j>>1, rl=(j&1)*2+((k>>3)&1), lane=(n&7)*4+((k>>1)&3), half=k&1
// -> per (ks,lane) the 16 b-regs for all 8 j are 4 contiguous conflict-free LDS.128.
__device__ __half g_gwH[512 * 256];   // 8 tiles
__device__ __half g_zH [256 * 256];   // 4 tiles

// ---- smem layout (bytes) ----
// Lifetimes: {A,B} bufs live in GEMM phases; gates(f32) overlaps them (written only
// after last phase-1 compute + sync; phase-3 B writes begin only after tree's last
// gates read + sync). gbs overlaps leaf_frag head (gbs dead after sigmoid + sync).
#define A_OFF(b)   ((unsigned)(b) * 8192u)              // A frag [64m][64k] fp16, x2
#define B_OFF(b)   (16384u + (unsigned)(b) * 32768u)    // B frag tile, x2 (ends 81920)
#define GATES_OFF  0u                                   // gates [64][257] f32 (65792 B)
#define LEAF_OFF   81920u                               // leaf_frag: 4 A-tiles x 8192 B
#define GBS_OFF    81920u                               // 256 f32 (overlaps leaf_frag head)
#define SMEM_BYTES 114688u
#define GGLS 257

__device__ __forceinline__ uint32_t smem_u32(const void* p) {
    uint32_t a;
    asm("{ .reg .u64 t; cvta.to.shared.u64 t, %1; cvt.u32.u64 %0, t; }" : "=r"(a) : "l"(p));
    return a;
}
#define CP_ASYNC16(dst, src) \
    asm volatile("cp.async.cg.shared.global [%0], [%1], 16;" :: "r"(dst), "l"(src) : "memory")
#define CP_COMMIT() asm volatile("cp.async.commit_group;" ::: "memory")
#define CP_WAIT(n)  asm volatile("cp.async.wait_group %0;" :: "n"(n) : "memory")

__device__ __forceinline__ void mma16(float* c, const uint32_t* a, uint32_t b0, uint32_t b1) {
    asm volatile("mma.sync.aligned.m16n8k16.row.col.f32.f16.f16.f32 "
        "{%0,%1,%2,%3}, {%4,%5,%6,%7}, {%8,%9}, {%0,%1,%2,%3};"
        : "+f"(c[0]), "+f"(c[1]), "+f"(c[2]), "+f"(c[3])
        : "r"(a[0]), "r"(a[1]), "r"(a[2]), "r"(a[3]), "r"(b0), "r"(b1));
}
__device__ __forceinline__ float sigmoidf_fast(float v) {
    return __fdividef(1.0f, 1.0f + __expf(-v));
}

// A-frag STS byte addr (Kc=64) for half-quad (row, q), q in 0..15, k0=4q
__device__ __forceinline__ uint32_t afrag_addr(int row, int q) {
    int ra = row >> 4, ks = q >> 2;
    int lane = (row & 7) * 4 + ((2 * q) & 3);
    int reg  = ((row >> 3) & 1) + 2 * ((q >> 1) & 1);
    return (uint32_t)((ra * 4 + ks) * 512 + lane * 16 + reg * 4);
}

// ---- prep kernel: output-centric; 8 B-layout halves -> one uint4 ----
__global__ void prep_kernel(const float* __restrict__ gw, const float* __restrict__ z) {
    const int t8g = (blockIdx.x * 256 + threadIdx.x) * 8;   // 96 blocks -> 196608 halves
    __half h[8];
    int t8 = (t8g < 131072) ? t8g : (t8g - 131072);
    // decode: half=bit0, rl bits1-2, lane bits3-7, q bits8-9, group bits10-13, tile 14+
    int lane = (t8 >> 3) & 31;
    int q    = (t8 >> 8) & 3;
    int grp  = (t8 >> 10) & 15;
    int tile = t8 >> 14;
    int ng = grp >> 2, ks = grp & 3;
    int n_base = ng * 64 + (lane >> 2);
    int k_base = tile * 64 + ks * 16 + ((lane & 3) << 1);
    if (t8g < 131072) {           // gw -> g_gwH
        #pragma unroll
        for (int i = 0; i < 8; i++) {
            int n = n_base + (2 * q + (i >> 2)) * 8;
            int k = k_base + ((i >> 1) & 1) * 8 + (i & 1);
            h[i] = (n < GATES) ? __float2half_rn(gw[k * GATES + n]) : __half(0.0f);
        }
        *(uint4*)&g_gwH[t8] = *(const uint4*)h;
    } else {                      // z -> g_zH  (n = out row, k = leaf)
        #pragma unroll
        for (int i = 0; i < 8; i++) {
            int n = n_base + (2 * q + (i >> 2)) * 8;
            int k = k_base + ((i >> 1) & 1) * 8 + (i & 1);
            h[i] = __float2half_rn(z[n * 256 + k]);
        }
        *(uint4*)&g_zH[t8] = *(const uint4*)h;
    }
}

// ---- main fused kernel: one CTA = 64 rows, 8 warps (32m x 64n), 2 CTAs/SM ----
extern "C" __global__ void __launch_bounds__(NT, 2)
softtree_h8_kernel(const float* __restrict__ x,
                   const float* __restrict__ gb,
                   float* __restrict__ out)
{
    extern __shared__ char smc[];
    float* gates = (float*)(smc + GATES_OFF);
    float* gbs   = (float*)(smc + GBS_OFF);
    const uint32_t sb = smem_u32(smc);

    const int tid  = threadIdx.x;
    const int lane = tid & 31;
    const int wid  = tid >> 5;       // 0..7
    const int mg   = wid & 1;        // rows mg*32 .. +31
    const int ng   = wid >> 1;       // cols ng*64 .. +63
    const int g    = lane >> 2;
    const int t4   = lane & 3;
    const int rbase = blockIdx.x * BM;

    gbs[tid] = (tid < GATES) ? gb[tid] : 0.0f;

    float acc[2][8][4];
    #pragma unroll
    for (int ra = 0; ra < 2; ra++)
        #pragma unroll
        for (int j = 0; j < 8; j++)
            #pragma unroll
            for (int e = 0; e < 4; e++) acc[ra][j][e] = 0.0f;

    uint32_t xh[8];

    auto issueB = [&](int buf, const __half* srcTile) {
        const char* s = (const char*)srcTile;
        #pragma unroll
        for (int j = 0; j < 8; j++) {
            uint32_t off = (uint32_t)(tid + j * NT) * 16u;
            CP_ASYNC16(sb + B_OFF(buf) + off, s + off);
        }
    };
    auto ldgA = [&](int t) {
        #pragma unroll
        for (int j = 0; j < 4; j++) {
            int f = j * NT + tid;            // 0..1023
            int row = f >> 4, q = f & 15;
            float4 v = *(const float4*)&x[(size_t)(rbase + row) * 512 + t * 64 + q * 4];
            __half2 h0 = __floats2half2_rn(v.x, v.y);
            __half2 h1 = __floats2half2_rn(v.z, v.w);
            xh[2 * j]     = *(uint32_t*)&h0;
            xh[2 * j + 1] = *(uint32_t*)&h1;
        }
    };
    auto stsA = [&](int buf) {
        #pragma unroll
        for (int j = 0; j < 4; j++) {
            int f = j * NT + tid;
            int row = f >> 4, q = f & 15;
            uint32_t a0 = afrag_addr(row, q);
            *(uint32_t*)(smc + A_OFF(buf) + a0)      = xh[2 * j];
            *(uint32_t*)(smc + A_OFF(buf) + a0 + 16) = xh[2 * j + 1];
        }
    };
    // GEMM inner loop: A via 2 LDS.128, B via 4 contiguous conflict-free LDS.128 per ks
    auto compute = [&](uint32_t a_base, int bb) {
        #pragma unroll
        for (int ks = 0; ks < 4; ks++) {
            uint32_t a0[4], a1[4];
            *(uint4*)a0 = *(const uint4*)(smc + a_base + (uint32_t)(((mg * 2)     * 4 + ks) * 512 + lane * 16));
            *(uint4*)a1 = *(const uint4*)(smc + a_base + (uint32_t)(((mg * 2 + 1) * 4 + ks) * 512 + lane * 16));
            #pragma unroll
            for (int q = 0; q < 4; q++) {
                uint32_t b[4];
                *(uint4*)b = *(const uint4*)(smc + B_OFF(bb)
                              + (uint32_t)((ng * 4 + ks) * 2048 + q * 512 + lane * 16));
                mma16(acc[0][2 * q],     a0, b[0], b[1]);
                mma16(acc[0][2 * q + 1], a0, b[2], b[3]);
                mma16(acc[1][2 * q],     a1, b[0], b[1]);
                mma16(acc[1][2 * q + 1], a1, b[2], b[3]);
            }
        }
    };

    // ============ Phase 1: logits = x @ gwT (8 K-tiles of 64, ONE sync/tile) ============
    issueB(0, g_gwH);  CP_COMMIT();
    ldgA(0);  stsA(0);  ldgA(1);

    #pragma unroll 1
    for (int u = 0; u < 8; u++) {
        CP_WAIT(0);
        __syncthreads();
        if (u < 7) {
            stsA((u + 1) & 1);
            issueB((u + 1) & 1, g_gwH + (size_t)(u + 1) * 16384);
            CP_COMMIT();
        }
        compute(A_OFF(u & 1), u & 1);
        if (u < 6) ldgA(u + 2);
    }
    __syncthreads();   // last compute retired; A/B dead -> gates region writable

    // ============ bias + sigmoid -> gates (f32) ============
    #pragma unroll
    for (int ra = 0; ra < 2; ra++)
        #pragma unroll
        for (int j = 0; j < 8; j++) {
            int row = mg * 32 + ra * 16 + g;
            int col = ng * 64 + j * 8 + 2 * t4;
            gates[row * GGLS + col]           = sigmoidf_fast(acc[ra][j][0] + gbs[col]);
            gates[row * GGLS + col + 1]       = sigmoidf_fast(acc[ra][j][1] + gbs[col + 1]);
            gates[(row + 8) * GGLS + col]     = sigmoidf_fast(acc[ra][j][2] + gbs[col]);
            gates[(row + 8) * GGLS + col + 1] = sigmoidf_fast(acc[ra][j][3] + gbs[col + 1]);
        }
    __syncthreads();   // gates visible; gbs dead -> leaf_frag (overlapping gbs) writable

    // ============ tree products (f32) -> leaf_frag (A-fragment layout, fp16) ============
    {
        const int r = tid & 63;
        const float* grow = &gates[r * GGLS];
        #pragma unroll
        for (int s = 0; s < 2; s++) {
            const int h8 = (tid >> 6) + 4 * s;   // 0..7, leaves h8*32 .. +31

            float p;
            { float g0 = grow[0];             p = (h8 >> 2) ? 1.0f - g0 : g0; }
            { float g1 = grow[1 + (h8 >> 2)]; p = ((h8 >> 1) & 1) ? p - p * g1 : p * g1; }
            { float g2 = grow[3 + (h8 >> 1)]; p = (h8 & 1) ? p - p * g2 : p * g2; }
            float Q1[2];
            { float gg = grow[7 + h8]; Q1[0] = p * gg; Q1[1] = p - Q1[0]; }
            float Q2[4];
            #pragma unroll
            for (int i = 0; i < 2; i++) {
                float gg = grow[15 + 2 * h8 + i];
                Q2[2 * i] = Q1[i] * gg; Q2[2 * i + 1] = Q1[i] - Q2[2 * i];
            }
            float Q3[8];
            #pragma unroll
            for (int i = 0; i < 4; i++) {
                float gg = grow[31 + 4 * h8 + i];
                Q3[2 * i] = Q2[i] * gg; Q3[2 * i + 1] = Q2[i] - Q3[2 * i];
            }
            // leaves quad i (l = h8*32 + 4i .. +3) -> A-frag tile h8>>1, q = (h8&1)*8 + i
            const uint32_t tbase = LEAF_OFF + (uint32_t)(h8 >> 1) * 8192u;
            #pragma unroll
            for (int i = 0; i < 8; i++) {
                float gg = grow[63 + 8 * h8 + i];
                float qa = Q3[i] * gg, qb = Q3[i] - qa;
                float g5a = grow[127 + 16 * h8 + 2 * i];
                float v0 = qa * g5a, v1 = qa - v0;
                float g5b = grow[127 + 16 * h8 + 2 * i + 1];
                float v2 = qb * g5b, v3 = qb - v2;
                uint32_t ad = tbase + afrag_addr(r, (h8 & 1) * 8 + i);
                *(__half2*)(smc + ad)      = __floats2half2_rn(v0, v1);
                *(__half2*)(smc + ad + 16) = __floats2half2_rn(v2, v3);
            }
        }
    }
    __syncthreads();   // all gates reads retired; leaf_frag complete -> B bufs reusable

    // ============ Phase 3: out = leaf @ z^T (4 K-tiles, A read in-place) ============
    #pragma unroll
    for (int ra = 0; ra < 2; ra++)
        #pragma unroll
        for (int j = 0; j < 8; j++)
            #pragma unroll
            for (int e = 0; e < 4; e++) acc[ra][j][e] = 0.0f;

    issueB(0, g_zH);  CP_COMMIT();

    #pragma unroll 1
    for (int u = 0; u < 4; u++) {
        CP_WAIT(0);
        __syncthreads();
        if (u < 3) {
            issueB((u + 1) & 1, g_zH + (size_t)(u + 1) * 16384);
            CP_COMMIT();
        }
        compute(LEAF_OFF + (uint32_t)u * 8192u, u & 1);
    }

    // ============ write out ============
    #pragma unroll
    for (int ra = 0; ra < 2; ra++)
        #pragma unroll
        for (int j = 0; j < 8; j++) {
            int row = rbase + mg * 32 + ra * 16 + g;
            int col = ng * 64 + j * 8 + 2 * t4;
            float2 s0, s1;
            s0.x = acc[ra][j][0]; s0.y = acc[ra][j][1];
            s1.x = acc[ra][j][2]; s1.y = acc[ra][j][3];
            *(float2*)&out[(size_t)row * 256 + col]       = s0;
            *(float2*)&out[(size_t)(row + 8) * 256 + col] = s1;
        }
}

extern "C" void kernel_launch(void* const* d_in, const int* in_sizes, int n_in,
                              void* d_out, int out_size)
{
    const float* x  = (const float*)d_in[0];   // [B, 512]
    const float* gw = (const float*)d_in[1];   // [512, 255]
    const float* gb = (const float*)d_in[2];   // [255]
    const float* z  = (const float*)d_in[3];   // [256, 256]
    float* out = (float*)d_out;                // [B, 256]

    const int B = in_sizes[0] / 512;

    prep_kernel<<<96, 256>>>(gw, z);

    cudaFuncSetAttribute(softtree_h8_kernel,
                         cudaFuncAttributeMaxDynamicSharedMemorySize, SMEM_BYTES);
    softtree_h8_kernel<<<B / BM, NT, SMEM_BYTES>>>(x, gb, out);
}

// round 15
// speedup vs baseline: 1.6209x; 1.0331x over previous
#include <cuda_runtime.h>
#include <cuda_fp16.h>
#include <cstdint>

#define GATES 255
#define BM    64
#define NT    256

// Fragment-major fp16 weights, Kc=64 tiles (rebuilt every call, deterministic).
// Per tile (32 KB): offset (ng*4+ks)*2048 + q*512 + lane*16 + reg*4  -> the ng-slice
// (8 KB) is contiguous at tile_base + ng*8192.
__device__ __half g_gwH[512 * 256];   // 8 tiles
__device__ __half g_zH [256 * 256];   // 4 tiles

// ---- smem layout (bytes) ----
#define A_OFF(b)   ((unsigned)(b) * 8192u)              // A frag [64m][64k] fp16, x2
#define B_OFF(b)   (16384u + (unsigned)(b) * 32768u)    // B frag tile, x2 (ends 81920)
#define GATES_OFF  0u                                   // gates [64][257] f32 (overlays A+B)
#define LEAF_OFF   81920u                               // leaf_frag: 4 A-tiles x 8192 B
#define GBS_OFF    81920u                               // 256 f32 (overlays leaf head)
#define SMEM_BYTES 114688u
#define GGLS 257

// named barriers: 1+mg (count 128) for A halves, 3+ng (count 64) for B slices
#define BARN(id, cnt) asm volatile("bar.sync %0, %1;" :: "r"(id), "r"(cnt) : "memory")

__device__ __forceinline__ uint32_t smem_u32(const void* p) {
    uint32_t a;
    asm("{ .reg .u64 t; cvta.to.shared.u64 t, %1; cvt.u32.u64 %0, t; }" : "=r"(a) : "l"(p));
    return a;
}
#define CP_ASYNC16(dst, src) \
    asm volatile("cp.async.cg.shared.global [%0], [%1], 16;" :: "r"(dst), "l"(src) : "memory")
#define CP_COMMIT() asm volatile("cp.async.commit_group;" ::: "memory")
#define CP_WAIT(n)  asm volatile("cp.async.wait_group %0;" :: "n"(n) : "memory")

__device__ __forceinline__ void mma16(float* c, const uint32_t* a, uint32_t b0, uint32_t b1) {
    asm volatile("mma.sync.aligned.m16n8k16.row.col.f32.f16.f16.f32 "
        "{%0,%1,%2,%3}, {%4,%5,%6,%7}, {%8,%9}, {%0,%1,%2,%3};"
        : "+f"(c[0]), "+f"(c[1]), "+f"(c[2]), "+f"(c[3])
        : "r"(a[0]), "r"(a[1]), "r"(a[2]), "r"(a[3]), "r"(b0), "r"(b1));
}
__device__ __forceinline__ float sigmoidf_fast(float v) {
    return __fdividef(1.0f, 1.0f + __expf(-v));
}

// A-frag STS byte addr (Kc=64) for half-quad (row, q), q in 0..15, k0=4q
__device__ __forceinline__ uint32_t afrag_addr(int row, int q) {
    int ra = row >> 4, ks = q >> 2;
    int lane = (row & 7) * 4 + ((2 * q) & 3);
    int reg  = ((row >> 3) & 1) + 2 * ((q >> 1) & 1);
    return (uint32_t)((ra * 4 + ks) * 512 + lane * 16 + reg * 4);
}

// ---- prep kernel (identical math to R14: verified by matching rel_err) ----
__global__ void prep_kernel(const float* __restrict__ gw, const float* __restrict__ z) {
    const int t8g = (blockIdx.x * 256 + threadIdx.x) * 8;   // 96 blocks -> 196608 halves
    __half h[8];
    int t8 = (t8g < 131072) ? t8g : (t8g - 131072);
    int lane = (t8 >> 3) & 31;
    int q    = (t8 >> 8) & 3;
    int grp  = (t8 >> 10) & 15;
    int tile = t8 >> 14;
    int ng = grp >> 2, ks = grp & 3;
    int n_base = ng * 64 + (lane >> 2);
    int k_base = tile * 64 + ks * 16 + ((lane & 3) << 1);
    if (t8g < 131072) {
        #pragma unroll
        for (int i = 0; i < 8; i++) {
            int n = n_base + (2 * q + (i >> 2)) * 8;
            int k = k_base + ((i >> 1) & 1) * 8 + (i & 1);
            h[i] = (n < GATES) ? __float2half_rn(gw[k * GATES + n]) : __half(0.0f);
        }
        *(uint4*)&g_gwH[t8] = *(const uint4*)h;
    } else {
        #pragma unroll
        for (int i = 0; i < 8; i++) {
            int n = n_base + (2 * q + (i >> 2)) * 8;
            int k = k_base + ((i >> 1) & 1) * 8 + (i & 1);
            h[i] = __float2half_rn(z[n * 256 + k]);
        }
        *(uint4*)&g_zH[t8] = *(const uint4*)h;
    }
}

// ---- main fused kernel: one CTA = 64 rows, 8 warps (32m x 64n), 2 CTAs/SM ----
extern "C" __global__ void __launch_bounds__(NT, 2)
softtree_h9_kernel(const float* __restrict__ x,
                   const float* __restrict__ gb,
                   float* __restrict__ out)
{
    extern __shared__ char smc[];
    float* gates = (float*)(smc + GATES_OFF);
    float* gbs   = (float*)(smc + GBS_OFF);
    const uint32_t sb = smem_u32(smc);

    const int tid  = threadIdx.x;
    const int lane = tid & 31;
    const int wid  = tid >> 5;       // 0..7
    const int mg   = wid & 1;        // rows mg*32 .. +31
    const int ng   = wid >> 1;       // cols ng*64 .. +63
    const int g    = lane >> 2;
    const int t4   = lane & 3;
    const int gt   = ng * 32 + lane; // index within mg-group (0..127)
    const int pt   = mg * 32 + lane; // index within ng-pair  (0..63)
    const int rbase = blockIdx.x * BM;

    gbs[tid] = (tid < GATES) ? gb[tid] : 0.0f;

    float acc[2][8][4];
    #pragma unroll
    for (int ra = 0; ra < 2; ra++)
        #pragma unroll
        for (int j = 0; j < 8; j++)
            #pragma unroll
            for (int e = 0; e < 4; e++) acc[ra][j][e] = 0.0f;

    uint32_t xh[8];

    // each ng-pair loads ITS OWN contiguous 8 KB B slice
    auto issueB = [&](int buf, const __half* srcTile) {
        const char* s = (const char*)srcTile + (uint32_t)ng * 8192u;
        const uint32_t d = sb + B_OFF(buf) + (uint32_t)ng * 8192u;
        #pragma unroll
        for (int j = 0; j < 8; j++) {
            uint32_t off = (uint32_t)(pt + j * 64) * 16u;
            CP_ASYNC16(d + off, s + off);
        }
    };
    // each mg-group stages ITS OWN 32-row A half (rows mg*32 .. +31)
    auto ldgA = [&](int t) {
        #pragma unroll
        for (int j = 0; j < 4; j++) {
            int f = j * 128 + gt;            // 0..511
            int rl = f >> 4, q = f & 15;
            float4 v = *(const float4*)&x[(size_t)(rbase + mg * 32 + rl) * 512 + t * 64 + q * 4];
            __half2 h0 = __floats2half2_rn(v.x, v.y);
            __half2 h1 = __floats2half2_rn(v.z, v.w);
            xh[2 * j]     = *(uint32_t*)&h0;
            xh[2 * j + 1] = *(uint32_t*)&h1;
        }
    };
    auto stsA = [&](int buf) {
        #pragma unroll
        for (int j = 0; j < 4; j++) {
            int f = j * 128 + gt;
            int rl = f >> 4, q = f & 15;
            uint32_t a0 = afrag_addr(mg * 32 + rl, q);
            *(uint32_t*)(smc + A_OFF(buf) + a0)      = xh[2 * j];
            *(uint32_t*)(smc + A_OFF(buf) + a0 + 16) = xh[2 * j + 1];
        }
    };
    auto compute = [&](uint32_t a_base, int bb) {
        #pragma unroll
        for (int ks = 0; ks < 4; ks++) {
            uint32_t a0[4], a1[4];
            *(uint4*)a0 = *(const uint4*)(smc + a_base + (uint32_t)(((mg * 2)     * 4 + ks) * 512 + lane * 16));
            *(uint4*)a1 = *(const uint4*)(smc + a_base + (uint32_t)(((mg * 2 + 1) * 4 + ks) * 512 + lane * 16));
            #pragma unroll
            for (int q = 0; q < 4; q++) {
                uint32_t b[4];
                *(uint4*)b = *(const uint4*)(smc + B_OFF(bb)
                              + (uint32_t)((ng * 4 + ks) * 2048 + q * 512 + lane * 16));
                mma16(acc[0][2 * q],     a0, b[0], b[1]);
                mma16(acc[0][2 * q + 1], a0, b[2], b[3]);
                mma16(acc[1][2 * q],     a1, b[0], b[1]);
                mma16(acc[1][2 * q + 1], a1, b[2], b[3]);
            }
        }
    };

    // ============ Phase 1: logits = x @ gwT (8 K-tiles; scoped barriers only) ============
    issueB(0, g_gwH);  CP_COMMIT();
    ldgA(0);  stsA(0);  ldgA(1);

    #pragma unroll 1
    for (int u = 0; u < 8; u++) {
        BARN(1 + mg, 128);                 // group done compute(u-1); A(u) visible
        if (u < 7) stsA((u + 1) & 1);      // stage A(u+1) (buf last read at u-1)
        CP_WAIT(0);                        // own B(u) landed
        BARN(3 + ng, 64);                  // pair's B(u) visible; pair done compute(u-1)
        if (u < 7) {
            issueB((u + 1) & 1, g_gwH + (size_t)(u + 1) * 16384);  // buf last read at u-1
            CP_COMMIT();
        }
        compute(A_OFF(u & 1), u & 1);
        if (u < 6) ldgA(u + 2);
    }
    __syncthreads();   // all warps' compute(7) retired -> gates region writable

    // ============ bias + sigmoid -> gates (f32) ============
    #pragma unroll
    for (int ra = 0; ra < 2; ra++)
        #pragma unroll
        for (int j = 0; j < 8; j++) {
            int row = mg * 32 + ra * 16 + g;
            int col = ng * 64 + j * 8 + 2 * t4;
            gates[row * GGLS + col]           = sigmoidf_fast(acc[ra][j][0] + gbs[col]);
            gates[row * GGLS + col + 1]       = sigmoidf_fast(acc[ra][j][1] + gbs[col + 1]);
            gates[(row + 8) * GGLS + col]     = sigmoidf_fast(acc[ra][j][2] + gbs[col]);
            gates[(row + 8) * GGLS + col + 1] = sigmoidf_fast(acc[ra][j][3] + gbs[col + 1]);
        }
    __syncthreads();   // gates visible; gbs dead -> leaf_frag writable

    // ============ tree products (f32) -> leaf_frag (A-fragment layout, fp16) ============
    {
        const int r = tid & 63;
        const float* grow = &gates[r * GGLS];
        #pragma unroll
        for (int s = 0; s < 2; s++) {
            const int h8 = (tid >> 6) + 4 * s;   // 0..7, leaves h8*32 .. +31

            float p;
            { float g0 = grow[0];             p = (h8 >> 2) ? 1.0f - g0 : g0; }
            { float g1 = grow[1 + (h8 >> 2)]; p = ((h8 >> 1) & 1) ? p - p * g1 : p * g1; }
            { float g2 = grow[3 + (h8 >> 1)]; p = (h8 & 1) ? p - p * g2 : p * g2; }
            float Q1[2];
            { float gg = grow[7 + h8]; Q1[0] = p * gg; Q1[1] = p - Q1[0]; }
            float Q2[4];
            #pragma unroll
            for (int i = 0; i < 2; i++) {
                float gg = grow[15 + 2 * h8 + i];
                Q2[2 * i] = Q1[i] * gg; Q2[2 * i + 1] = Q1[i] - Q2[2 * i];
            }
            float Q3[8];
            #pragma unroll
            for (int i = 0; i < 4; i++) {
                float gg = grow[31 + 4 * h8 + i];
                Q3[2 * i] = Q2[i] * gg; Q3[2 * i + 1] = Q2[i] - Q3[2 * i];
            }
            const uint32_t tbase = LEAF_OFF + (uint32_t)(h8 >> 1) * 8192u;
            #pragma unroll
            for (int i = 0; i < 8; i++) {
                float gg = grow[63 + 8 * h8 + i];
                float qa = Q3[i] * gg, qb = Q3[i] - qa;
                float g5a = grow[127 + 16 * h8 + 2 * i];
                float v0 = qa * g5a, v1 = qa - v0;
                float g5b = grow[127 + 16 * h8 + 2 * i + 1];
                float v2 = qb * g5b, v3 = qb - v2;
                uint32_t ad = tbase + afrag_addr(r, (h8 & 1) * 8 + i);
                *(__half2*)(smc + ad)      = __floats2half2_rn(v0, v1);
                *(__half2*)(smc + ad + 16) = __floats2half2_rn(v2, v3);
            }
        }
    }
    __syncthreads();   // leaf_frag complete everywhere; B bufs reusable

    // ============ Phase 3: out = leaf @ z^T (4 K-tiles; pair barriers only) ============
    #pragma unroll
    for (int ra = 0; ra < 2; ra++)
        #pragma unroll
        for (int j = 0; j < 8; j++)
            #pragma unroll
            for (int e = 0; e < 4; e++) acc[ra][j][e] = 0.0f;

    issueB(0, g_zH);  CP_COMMIT();

    #pragma unroll 1
    for (int u = 0; u < 4; u++) {
        CP_WAIT(0);
        BARN(3 + ng, 64);                  // pair B(u) visible; pair done compute(u-1)
        if (u < 3) {
            issueB((u + 1) & 1, g_zH + (size_t)(u + 1) * 16384);
            CP_COMMIT();
        }
        compute(LEAF_OFF + (uint32_t)u * 8192u, u & 1);
    }

    // ============ write out ============
    #pragma unroll
    for (int ra = 0; ra < 2; ra++)
        #pragma unroll
        for (int j = 0; j < 8; j++) {
            int row = rbase + mg * 32 + ra * 16 + g;
            int col = ng * 64 + j * 8 + 2 * t4;
            float2 s0, s1;
            s0.x = acc[ra][j][0]; s0.y = acc[ra][j][1];
            s1.x = acc[ra][j][2]; s1.y = acc[ra][j][3];
            *(float2*)&out[(size_t)row * 256 + col]       = s0;
            *(float2*)&out[(size_t)(row + 8) * 256 + col] = s1;
        }
}

extern "C" void kernel_launch(void* const* d_in, const int* in_sizes, int n_in,
                              void* d_out, int out_size)
{
    const float* x  = (const float*)d_in[0];   // [B, 512]
    const float* gw = (const float*)d_in[1];   // [512, 255]
    const float* gb = (const float*)d_in[2];   // [255]
    const float* z  = (const float*)d_in[3];   // [256, 256]
    float* out = (float*)d_out;                // [B, 256]

    const int B = in_sizes[0] / 512;

    prep_kernel<<<96, 256>>>(gw, z);

    cudaFuncSetAttribute(softtree_h9_kernel,
                         cudaFuncAttributeMaxDynamicSharedMemorySize, SMEM_BYTES);
    softtree_h9_kernel<<<B / BM, NT, SMEM_BYTES>>>(x, gb, out);
}

// round 16
// speedup vs baseline: 1.6565x; 1.0220x over previous
#include <cuda_runtime.h>
#include <cuda_fp16.h>
#include <cstdint>

#define GATES 255
#define BM    64
#define NT    256

// Fragment-major fp16 weights, Kc=64 tiles (rebuilt every call, deterministic).
// Per tile (32 KB): offset (ng*4+ks)*2048 + q*512 + lane*16 + reg*4 -> ng-slice
// (8 KB) contiguous at tile_base + ng*8192.
__device__ __half g_gwH[512 * 256];   // 8 tiles
__device__ __half g_zH [256 * 256];   // 4 tiles

// ---- smem layout (bytes) ----
// Phase 1: A 2x8KB + B 3x32KB (third B buffer borrows the leaf region).
// gates f32 (65792 B) overlays A+B0+B1 after phase 1 (sync-separated).
// leaf_frag overlays B2 after phase 1. Phase 3: A in-place from leaf_frag,
// B double-buffered in B0/B1 (gates dead by then).
#define A_OFF(b)   ((unsigned)(b) * 8192u)    // A frag [64m][64k] fp16, x2
#define GATES_OFF  0u                         // gates [64][257] f32
#define LEAF_OFF   81920u                     // leaf_frag: 4 A-tiles x 8192 B (= B buf 2)
#define SMEM_BYTES 114688u
#define GGLS 257

__device__ __constant__ uint32_t BOFF[3] = {16384u, 49152u, 81920u};

// named barriers: 1+mg (count 128) for A halves, 3+ng (count 64) for B slices
#define BARN(id, cnt) asm volatile("bar.sync %0, %1;" :: "r"(id), "r"(cnt) : "memory")

__device__ __forceinline__ uint32_t smem_u32(const void* p) {
    uint32_t a;
    asm("{ .reg .u64 t; cvta.to.shared.u64 t, %1; cvt.u32.u64 %0, t; }" : "=r"(a) : "l"(p));
    return a;
}
#define CP_ASYNC16(dst, src) \
    asm volatile("cp.async.cg.shared.global [%0], [%1], 16;" :: "r"(dst), "l"(src) : "memory")
#define CP_COMMIT() asm volatile("cp.async.commit_group;" ::: "memory")
#define CP_WAIT(n)  asm volatile("cp.async.wait_group %0;" :: "n"(n) : "memory")

__device__ __forceinline__ void mma16(float* c, const uint32_t* a, uint32_t b0, uint32_t b1) {
    asm volatile("mma.sync.aligned.m16n8k16.row.col.f32.f16.f16.f32 "
        "{%0,%1,%2,%3}, {%4,%5,%6,%7}, {%8,%9}, {%0,%1,%2,%3};"
        : "+f"(c[0]), "+f"(c[1]), "+f"(c[2]), "+f"(c[3])
        : "r"(a[0]), "r"(a[1]), "r"(a[2]), "r"(a[3]), "r"(b0), "r"(b1));
}
__device__ __forceinline__ float sigmoidf_fast(float v) {
    return __fdividef(1.0f, 1.0f + __expf(-v));
}

// A-frag STS byte addr (Kc=64) for half-quad (row, q), q in 0..15, k0=4q
__device__ __forceinline__ uint32_t afrag_addr(int row, int q) {
    int ra = row >> 4, ks = q >> 2;
    int lane = (row & 7) * 4 + ((2 * q) & 3);
    int reg  = ((row >> 3) & 1) + 2 * ((q >> 1) & 1);
    return (uint32_t)((ra * 4 + ks) * 512 + lane * 16 + reg * 4);
}

// ---- prep kernel (identical math to R14/R15) ----
__global__ void prep_kernel(const float* __restrict__ gw, const float* __restrict__ z) {
    const int t8g = (blockIdx.x * 256 + threadIdx.x) * 8;   // 96 blocks -> 196608 halves
    __half h[8];
    int t8 = (t8g < 131072) ? t8g : (t8g - 131072);
    int lane = (t8 >> 3) & 31;
    int q    = (t8 >> 8) & 3;
    int grp  = (t8 >> 10) & 15;
    int tile = t8 >> 14;
    int ng = grp >> 2, ks = grp & 3;
    int n_base = ng * 64 + (lane >> 2);
    int k_base = tile * 64 + ks * 16 + ((lane & 3) << 1);
    if (t8g < 131072) {
        #pragma unroll
        for (int i = 0; i < 8; i++) {
            int n = n_base + (2 * q + (i >> 2)) * 8;
            int k = k_base + ((i >> 1) & 1) * 8 + (i & 1);
            h[i] = (n < GATES) ? __float2half_rn(gw[k * GATES + n]) : __half(0.0f);
        }
        *(uint4*)&g_gwH[t8] = *(const uint4*)h;
    } else {
        #pragma unroll
        for (int i = 0; i < 8; i++) {
            int n = n_base + (2 * q + (i >> 2)) * 8;
            int k = k_base + ((i >> 1) & 1) * 8 + (i & 1);
            h[i] = __float2half_rn(z[n * 256 + k]);
        }
        *(uint4*)&g_zH[t8] = *(const uint4*)h;
    }
}

// ---- main fused kernel: one CTA = 64 rows, 8 warps (32m x 64n), 2 CTAs/SM ----
extern "C" __global__ void __launch_bounds__(NT, 2)
softtree_h10_kernel(const float* __restrict__ x,
                    const float* __restrict__ gb,
                    float* __restrict__ out)
{
    extern __shared__ char smc[];
    float* gates = (float*)(smc + GATES_OFF);
    const uint32_t sb = smem_u32(smc);

    const int tid  = threadIdx.x;
    const int lane = tid & 31;
    const int wid  = tid >> 5;       // 0..7
    const int mg   = wid & 1;        // rows mg*32 .. +31
    const int ng   = wid >> 1;       // cols ng*64 .. +63
    const int g    = lane >> 2;
    const int t4   = lane & 3;
    const int gt   = ng * 32 + lane; // index within mg-group (0..127)
    const int pt   = mg * 32 + lane; // index within ng-pair  (0..63)
    const int rbase = blockIdx.x * BM;

    float acc[2][8][4];
    #pragma unroll
    for (int ra = 0; ra < 2; ra++)
        #pragma unroll
        for (int j = 0; j < 8; j++)
            #pragma unroll
            for (int e = 0; e < 4; e++) acc[ra][j][e] = 0.0f;

    uint32_t xh[8];

    // each ng-pair loads ITS OWN contiguous 8 KB B slice into the given buffer
    auto issueB = [&](uint32_t bbase, const __half* srcTile) {
        const char* s = (const char*)srcTile + (uint32_t)ng * 8192u;
        const uint32_t d = sb + bbase + (uint32_t)ng * 8192u;
        #pragma unroll
        for (int j = 0; j < 8; j++) {
            uint32_t off = (uint32_t)(pt + j * 64) * 16u;
            CP_ASYNC16(d + off, s + off);
        }
    };
    // each mg-group stages ITS OWN 32-row A half (rows mg*32 .. +31)
    auto ldgA = [&](int t) {
        #pragma unroll
        for (int j = 0; j < 4; j++) {
            int f = j * 128 + gt;            // 0..511
            int rl = f >> 4, q = f & 15;
            float4 v = *(const float4*)&x[(size_t)(rbase + mg * 32 + rl) * 512 + t * 64 + q * 4];
            __half2 h0 = __floats2half2_rn(v.x, v.y);
            __half2 h1 = __floats2half2_rn(v.z, v.w);
            xh[2 * j]     = *(uint32_t*)&h0;
            xh[2 * j + 1] = *(uint32_t*)&h1;
        }
    };
    auto stsA = [&](int buf) {
        #pragma unroll
        for (int j = 0; j < 4; j++) {
            int f = j * 128 + gt;
            int rl = f >> 4, q = f & 15;
            uint32_t a0 = afrag_addr(mg * 32 + rl, q);
            *(uint32_t*)(smc + A_OFF(buf) + a0)      = xh[2 * j];
            *(uint32_t*)(smc + A_OFF(buf) + a0 + 16) = xh[2 * j + 1];
        }
    };
    auto compute = [&](uint32_t a_base, uint32_t b_base) {
        #pragma unroll
        for (int ks = 0; ks < 4; ks++) {
            uint32_t a0[4], a1[4];
            *(uint4*)a0 = *(const uint4*)(smc + a_base + (uint32_t)(((mg * 2)     * 4 + ks) * 512 + lane * 16));
            *(uint4*)a1 = *(const uint4*)(smc + a_base + (uint32_t)(((mg * 2 + 1) * 4 + ks) * 512 + lane * 16));
            #pragma unroll
            for (int q = 0; q < 4; q++) {
                uint32_t b[4];
                *(uint4*)b = *(const uint4*)(smc + b_base
                              + (uint32_t)((ng * 4 + ks) * 2048 + q * 512 + lane * 16));
                mma16(acc[0][2 * q],     a0, b[0], b[1]);
                mma16(acc[0][2 * q + 1], a0, b[2], b[3]);
                mma16(acc[1][2 * q],     a1, b[0], b[1]);
                mma16(acc[1][2 * q + 1], a1, b[2], b[3]);
            }
        }
    };

    // ============ Phase 1: logits = x @ gwT (8 K-tiles; 3-deep B, scoped barriers) ============
    issueB(BOFF[0], g_gwH);          CP_COMMIT();
    issueB(BOFF[1], g_gwH + 16384);  CP_COMMIT();
    ldgA(0);  stsA(0);  ldgA(1);

    #pragma unroll 1
    for (int u = 0; u < 8; u++) {
        BARN(1 + mg, 128);                 // group done compute(u-1); A(u) visible
        if (u < 7) stsA((u + 1) & 1);
        if (u < 7) { CP_WAIT(1); } else { CP_WAIT(0); }   // own B(u) landed
        BARN(3 + ng, 64);                  // pair's B(u) visible; pair done compute(u-1)
        if (u < 6) {
            issueB(BOFF[(u + 2) % 3], g_gwH + (size_t)(u + 2) * 16384);  // 2 tiles ahead
            CP_COMMIT();
        }
        compute(A_OFF(u & 1), BOFF[u % 3]);
        if (u < 6) ldgA(u + 2);
    }
    __syncthreads();   // all compute(7) retired; A/B0/B1/B2 dead -> gates writable

    // ============ bias + sigmoid -> gates (f32; bias straight from global) ============
    #pragma unroll
    for (int ra = 0; ra < 2; ra++)
        #pragma unroll
        for (int j = 0; j < 8; j++) {
            int row = mg * 32 + ra * 16 + g;
            int col = ng * 64 + j * 8 + 2 * t4;
            float b0 = gb[col];                               // col <= 254 always
            float b1 = (col + 1 < GATES) ? gb[col + 1] : 0.0f;
            gates[row * GGLS + col]           = sigmoidf_fast(acc[ra][j][0] + b0);
            gates[row * GGLS + col + 1]       = sigmoidf_fast(acc[ra][j][1] + b1);
            gates[(row + 8) * GGLS + col]     = sigmoidf_fast(acc[ra][j][2] + b0);
            gates[(row + 8) * GGLS + col + 1] = sigmoidf_fast(acc[ra][j][3] + b1);
        }
    __syncthreads();   // gates visible; B2 region (leaf_frag) writable

    // ============ tree products (f32) -> leaf_frag (A-fragment layout, fp16) ============
    {
        const int r = tid & 63;
        const float* grow = &gates[r * GGLS];
        #pragma unroll
        for (int s = 0; s < 2; s++) {
            const int h8 = (tid >> 6) + 4 * s;   // 0..7, leaves h8*32 .. +31

            float p;
            { float g0 = grow[0];             p = (h8 >> 2) ? 1.0f - g0 : g0; }
            { float g1 = grow[1 + (h8 >> 2)]; p = ((h8 >> 1) & 1) ? p - p * g1 : p * g1; }
            { float g2 = grow[3 + (h8 >> 1)]; p = (h8 & 1) ? p - p * g2 : p * g2; }
            float Q1[2];
            { float gg = grow[7 + h8]; Q1[0] = p * gg; Q1[1] = p - Q1[0]; }
            float Q2[4];
            #pragma unroll
            for (int i = 0; i < 2; i++) {
                float gg = grow[15 + 2 * h8 + i];
                Q2[2 * i] = Q1[i] * gg; Q2[2 * i + 1] = Q1[i] - Q2[2 * i];
            }
            float Q3[8];
            #pragma unroll
            for (int i = 0; i < 4; i++) {
                float gg = grow[31 + 4 * h8 + i];
                Q3[2 * i] = Q2[i] * gg; Q3[2 * i + 1] = Q2[i] - Q3[2 * i];
            }
            const uint32_t tbase = LEAF_OFF + (uint32_t)(h8 >> 1) * 8192u;
            #pragma unroll
            for (int i = 0; i < 8; i++) {
                float gg = grow[63 + 8 * h8 + i];
                float qa = Q3[i] * gg, qb = Q3[i] - qa;
                float g5a = grow[127 + 16 * h8 + 2 * i];
                float v0 = qa * g5a, v1 = qa - v0;
                float g5b = grow[127 + 16 * h8 + 2 * i + 1];
                float v2 = qb * g5b, v3 = qb - v2;
                uint32_t ad = tbase + afrag_addr(r, (h8 & 1) * 8 + i);
                *(__half2*)(smc + ad)      = __floats2half2_rn(v0, v1);
                *(__half2*)(smc + ad + 16) = __floats2half2_rn(v2, v3);
            }
        }
    }
    __syncthreads();   // gates reads retired; leaf_frag complete -> B0/B1 reusable

    // ============ Phase 3: out = leaf @ z^T (4 K-tiles; pair barriers only) ============
    #pragma unroll
    for (int ra = 0; ra < 2; ra++)
        #pragma unroll
        for (int j = 0; j < 8; j++)
            #pragma unroll
            for (int e = 0; e < 4; e++) acc[ra][j][e] = 0.0f;

    issueB(BOFF[0], g_zH);  CP_COMMIT();

    #pragma unroll 1
    for (int u = 0; u < 4; u++) {
        CP_WAIT(0);
        BARN(3 + ng, 64);                  // pair B(u) visible; pair done compute(u-1)
        if (u < 3) {
            issueB(BOFF[(u + 1) & 1], g_zH + (size_t)(u + 1) * 16384);
            CP_COMMIT();
        }
        compute(LEAF_OFF + (uint32_t)u * 8192u, BOFF[u & 1]);
    }

    // ============ write out ============
    #pragma unroll
    for (int ra = 0; ra < 2; ra++)
        #pragma unroll
        for (int j = 0; j < 8; j++) {
            int row = rbase + mg * 32 + ra * 16 + g;
            int col = ng * 64 + j * 8 + 2 * t4;
            float2 s0, s1;
            s0.x = acc[ra][j][0]; s0.y = acc[ra][j][1];
            s1.x = acc[ra][j][2]; s1.y = acc[ra][j][3];
            *(float2*)&out[(size_t)row * 256 + col]       = s0;
            *(float2*)&out[(size_t)(row + 8) * 256 + col] = s1;
        }
}

extern "C" void kernel_launch(void* const* d_in, const int* in_sizes, int n_in,
                              void* d_out, int out_size)
{
    const float* x  = (const float*)d_in[0];   // [B, 512]
    const float* gw = (const float*)d_in[1];   // [512, 255]
    const float* gb = (const float*)d_in[2];   // [255]
    const float* z  = (const float*)d_in[3];   // [256, 256]
    float* out = (float*)d_out;                // [B, 256]

    const int B = in_sizes[0] / 512;

    prep_kernel<<<96, 256>>>(gw, z);

    cudaFuncSetAttribute(softtree_h10_kernel,
                         cudaFuncAttributeMaxDynamicSharedMemorySize, SMEM_BYTES);
    softtree_h10_kernel<<<B / BM, NT, SMEM_BYTES>>>(x, gb, out);
}